// round 2
// baseline (speedup 1.0000x reference)
#include <cuda_runtime.h>
#include <cstdint>

// ---------------------------------------------------------------------------
// MultiMolNet: per-atom type-routed 3-layer MLP, reduced over atoms per batch.
// Key identity:  sum over all types of MLP_t(masked feats)
//              = MLP_{type(atom)}(feats) + C - c_{type(atom)},  c_t = MLP_t(0)
// ---------------------------------------------------------------------------

#define FFMA2(acc, a, b) \
    asm("fma.rn.f32x2 %0, %1, %2, %0;" : "+l"(acc) : "l"(a), "l"(b))

__device__ __forceinline__ float hsum2(unsigned long long v) {
    return __uint_as_float((unsigned)v) + __uint_as_float((unsigned)(v >> 32));
}

__device__ float g_c[8];
__device__ float g_C;

constexpr int Bq   = 4096;
constexpr int Aq   = 64;
constexpr int Fq   = 124;   // feature count
constexpr int Tq   = 8;
constexpr int H1q  = 64;
constexpr int H2q  = 16;
constexpr int ROWS = 2;              // molecule rows per CTA
constexpr int ATOMS = ROWS * Aq;     // 128
constexpr int THREADS = 256;
constexpr int FP   = Fq;             // feats / W1 row stride (floats), 496B (16B mult)
constexpr int H1P  = 68;             // padded stride for h1 / W2T rows (272B, 16B mult)

// smem size in bytes (see layout in kernel)
constexpr int SMEM_FLOATS =
    ATOMS * FP      // featsS
  + H1q * FP        // W1s (transposed)
  + H2q * H1P       // W2Ts
  + 16 * H1P        // h1S (4 pairs * 4 atoms)
  + H1q             // b1s
  + ATOMS           // yS
  + ATOMS           // maskS
  + H2q             // b2s
  + H2q;            // W3s
constexpr int SMEM_INTS = 3 * ATOMS + 2 * Tq;   // typeS, rankS, orderS, cnt, off
constexpr int SMEM_BYTES = (SMEM_FLOATS + SMEM_INTS) * 4;

// ---------------------------------------------------------------------------
// Precompute c_t = MLP_t(0) and C = sum_t c_t   (one tiny block)
// ---------------------------------------------------------------------------
__global__ void mol_precompute(const float* __restrict__ b1,
                               const float* __restrict__ W2,
                               const float* __restrict__ b2,
                               const float* __restrict__ W3,
                               const float* __restrict__ b3) {
    __shared__ float cs[Tq];
    int wid = threadIdx.x >> 5, lane = threadIdx.x & 31;
    if (wid < Tq && lane < H2q) {
        int t = wid, g = lane;
        float acc = b2[t * H2q + g];
        #pragma unroll 8
        for (int h = 0; h < H1q; h++) {
            float r = fmaxf(b1[t * H1q + h], 0.f);
            acc = fmaf(r, W2[(t * H1q + h) * H2q + g], acc);
        }
        float p = fmaxf(acc, 0.f) * W3[t * H2q + g];
        p += __shfl_xor_sync(0x0000ffffu, p, 8);
        p += __shfl_xor_sync(0x0000ffffu, p, 4);
        p += __shfl_xor_sync(0x0000ffffu, p, 2);
        p += __shfl_xor_sync(0x0000ffffu, p, 1);
        if (g == 0) cs[t] = p + b3[t];
    }
    __syncthreads();
    if (threadIdx.x == 0) {
        float s = 0.f;
        for (int t = 0; t < Tq; t++) { g_c[t] = cs[t]; s += cs[t]; }
        g_C = s;
    }
}

// ---------------------------------------------------------------------------
// Main kernel: one CTA = 2 molecule rows = 128 atoms.
// ---------------------------------------------------------------------------
__global__ __launch_bounds__(THREADS, 2)
void mol_main(const float* __restrict__ x,  const float* __restrict__ mask,
              const float* __restrict__ W1, const float* __restrict__ b1,
              const float* __restrict__ W2, const float* __restrict__ b2,
              const float* __restrict__ W3, const float* __restrict__ b3,
              float* __restrict__ out) {
    extern __shared__ __align__(16) char smraw[];
    float* featsS = (float*)smraw;            // [128][124]
    float* W1s    = featsS + ATOMS * FP;      // [64][124]  (W1 transposed: [out][k])
    float* W2Ts   = W1s + H1q * FP;           // [16][68]   (W2 transposed: [g][h])
    float* h1S    = W2Ts + H2q * H1P;         // [4 pairs][4 atoms][68]
    float* b1s    = h1S + 16 * H1P;           // [64]
    float* yS     = b1s + H1q;                // [128]  per-atom result (pre-mask)
    float* maskS  = yS + ATOMS;               // [128]
    float* b2s    = maskS + ATOMS;            // [16]
    float* W3s    = b2s + H2q;                // [16]
    int*   typeS  = (int*)(W3s + H2q);        // [128]
    int*   rankS  = typeS + ATOMS;            // [128]
    int*   orderS = rankS + ATOMS;            // [128]
    int*   cnt    = orderS + ATOMS;           // [8]
    int*   off    = cnt + Tq;                 // [8]

    const int tid  = threadIdx.x;
    const int lane = tid & 31;
    const int wid  = tid >> 5;
    const int pair = wid >> 1;     // 0..3
    const int hw   = wid & 1;      // which half of outputs
    const int j    = hw * 32 + lane;     // my h1 output index (0..63)
    const int barid = pair + 1;

    // ---- load & parse x slice (128 atoms * 125 floats), coalesced
    const float* xblk = x + (size_t)blockIdx.x * (ATOMS * (Fq + 1));
    for (int e = tid; e < ATOMS * (Fq + 1); e += THREADS) {
        int atom = e / 125;
        int pos  = e - atom * 125;
        float v  = xblk[e];
        if (pos == 0) typeS[atom] = (int)v;
        else          featsS[atom * FP + (pos - 1)] = v;
    }
    if (tid < ATOMS) maskS[tid] = mask[(size_t)blockIdx.x * ATOMS + tid];
    if (tid < Tq) cnt[tid] = 0;
    __syncthreads();
    if (tid < ATOMS) rankS[tid] = atomicAdd(&cnt[typeS[tid]], 1);
    __syncthreads();
    if (tid == 0) {
        int s = 0;
        for (int t = 0; t < Tq; t++) { off[t] = s; s += cnt[t]; }
    }
    __syncthreads();
    if (tid < ATOMS) orderS[off[typeS[tid]] + rankS[tid]] = tid;
    __syncthreads();

    // ---- per-type loop
    for (int t = 0; t < Tq; t++) {
        const int n = cnt[t];
        if (n == 0) continue;                 // uniform across CTA
        __syncthreads();                      // previous type's compute done

        // stage W1[t] transposed: W1s[j][k] = W1[t][k][j]  (global read coalesced)
        for (int e = tid; e < H1q * Fq; e += THREADS) {
            int k = e >> 6, jj = e & 63;
            W1s[jj * FP + k] = W1[t * (H1q * Fq) + e];
        }
        // stage W2[t] transposed: W2Ts[g][h] = W2[t][h][g]
        for (int e = tid; e < H1q * H2q; e += THREADS) {
            int h = e >> 4, g = e & 15;
            W2Ts[g * H1P + h] = W2[t * (H1q * H2q) + e];
        }
        if (tid < H1q) b1s[tid] = b1[t * H1q + tid];
        if (tid < H2q) { b2s[tid] = b2[t * H2q + tid]; W3s[tid] = W3[t * H2q + tid]; }
        __syncthreads();

        const float b1j = b1s[j];
        const float ct  = g_c[t];
        const float b3v = b3[t];
        const int base  = off[t];
        const ulonglong2* wrow =
            reinterpret_cast<const ulonglong2*>(W1s + j * FP);

        // warp-pair processes groups of 4 atoms
        for (int g0 = pair * 4; g0 < n; g0 += 16) {
            int i0 = orderS[base + min(g0 + 0, n - 1)];
            int i1 = orderS[base + min(g0 + 1, n - 1)];
            int i2 = orderS[base + min(g0 + 2, n - 1)];
            int i3 = orderS[base + min(g0 + 3, n - 1)];
            const ulonglong2* fr0 = reinterpret_cast<const ulonglong2*>(featsS + i0 * FP);
            const ulonglong2* fr1 = reinterpret_cast<const ulonglong2*>(featsS + i1 * FP);
            const ulonglong2* fr2 = reinterpret_cast<const ulonglong2*>(featsS + i2 * FP);
            const ulonglong2* fr3 = reinterpret_cast<const ulonglong2*>(featsS + i3 * FP);

            // layer 1: lane computes h1[j] for 4 atoms; k packed in f32x2 pairs
            unsigned long long a0x = 0, a0y = 0, a1x = 0, a1y = 0;
            unsigned long long a2x = 0, a2y = 0, a3x = 0, a3y = 0;
            #pragma unroll
            for (int kk = 0; kk < 31; kk++) {       // 31 * 4 = 124 features
                ulonglong2 w  = wrow[kk];           // (w_k,w_k+1),(w_k+2,w_k+3)
                ulonglong2 f0 = fr0[kk];
                ulonglong2 f1 = fr1[kk];
                ulonglong2 f2 = fr2[kk];
                ulonglong2 f3 = fr3[kk];
                FFMA2(a0x, w.x, f0.x); FFMA2(a0y, w.y, f0.y);
                FFMA2(a1x, w.x, f1.x); FFMA2(a1y, w.y, f1.y);
                FFMA2(a2x, w.x, f2.x); FFMA2(a2y, w.y, f2.y);
                FFMA2(a3x, w.x, f3.x); FFMA2(a3y, w.y, f3.y);
            }
            float* hb = h1S + pair * 4 * H1P;
            hb[0 * H1P + j] = fmaxf(hsum2(a0x) + hsum2(a0y) + b1j, 0.f);
            hb[1 * H1P + j] = fmaxf(hsum2(a1x) + hsum2(a1y) + b1j, 0.f);
            hb[2 * H1P + j] = fmaxf(hsum2(a2x) + hsum2(a2y) + b1j, 0.f);
            hb[3 * H1P + j] = fmaxf(hsum2(a3x) + hsum2(a3y) + b1j, 0.f);
            asm volatile("bar.sync %0, %1;" :: "r"(barid), "r"(64) : "memory");

            // layer 2 + 3: 64 lanes = 4 atoms x 16 outputs
            {
                const int aslot = j >> 4;           // 0..3
                const int g     = j & 15;           // h2 output index
                const ulonglong2* hr =
                    reinterpret_cast<const ulonglong2*>(h1S + (pair * 4 + aslot) * H1P);
                const ulonglong2* w2r =
                    reinterpret_cast<const ulonglong2*>(W2Ts + g * H1P);
                unsigned long long bx = 0, by = 0;
                #pragma unroll
                for (int hh = 0; hh < 16; hh++) {   // 16 * 4 = 64 hidden
                    ulonglong2 hv = hr[hh];
                    ulonglong2 wv = w2r[hh];
                    FFMA2(bx, hv.x, wv.x); FFMA2(by, hv.y, wv.y);
                }
                float h2 = fmaxf(hsum2(bx) + hsum2(by) + b2s[g], 0.f);
                float p  = h2 * W3s[g];
                p += __shfl_xor_sync(0xffffffffu, p, 8);
                p += __shfl_xor_sync(0xffffffffu, p, 4);
                p += __shfl_xor_sync(0xffffffffu, p, 2);
                p += __shfl_xor_sync(0xffffffffu, p, 1);
                if (g == 0 && (g0 + aslot) < n) {
                    int atom = orderS[base + g0 + aslot];
                    yS[atom] = p + b3v - ct;        // + C applied at reduce
                }
            }
            asm volatile("bar.sync %0, %1;" :: "r"(barid), "r"(64) : "memory");
        }
    }
    __syncthreads();

    // ---- deterministic per-row reduce: out[b] = sum(mask*y) + C * sum(mask)
    if (wid == 0) {
        const float Cv = g_C;
        #pragma unroll
        for (int r = 0; r < ROWS; r++) {
            float m0 = maskS[r * Aq + lane];
            float m1 = maskS[r * Aq + lane + 32];
            float v  = m0 * yS[r * Aq + lane] + m1 * yS[r * Aq + lane + 32];
            float m  = m0 + m1;
            #pragma unroll
            for (int o = 16; o; o >>= 1) {
                v += __shfl_xor_sync(0xffffffffu, v, o);
                m += __shfl_xor_sync(0xffffffffu, m, o);
            }
            if (lane == 0) out[blockIdx.x * ROWS + r] = v + Cv * m;
        }
    }
}

// ---------------------------------------------------------------------------
extern "C" void kernel_launch(void* const* d_in, const int* in_sizes, int n_in,
                              void* d_out, int out_size) {
    const float* x  = (const float*)d_in[0];
    const float* mk = (const float*)d_in[1];
    const float* W1 = (const float*)d_in[2];
    const float* b1 = (const float*)d_in[3];
    const float* W2 = (const float*)d_in[4];
    const float* b2 = (const float*)d_in[5];
    const float* W3 = (const float*)d_in[6];
    const float* b3 = (const float*)d_in[7];
    float* out = (float*)d_out;

    cudaFuncSetAttribute(mol_main, cudaFuncAttributeMaxDynamicSharedMemorySize,
                         SMEM_BYTES);

    mol_precompute<<<1, 256>>>(b1, W2, b2, W3, b3);
    mol_main<<<Bq / ROWS, THREADS, SMEM_BYTES>>>(x, mk, W1, b1, W2, b2, W3, b3, out);
}

// round 3
// speedup vs baseline: 2.4486x; 2.4486x over previous
#include <cuda_runtime.h>
#include <cstdint>

// ---------------------------------------------------------------------------
// MultiMolNet: type-routed 3-layer MLP per atom.
// Identity: sum_t' MLP_t'(masked feats) = MLP_t(feats) + C - c_t,  c_t=MLP_t(0)
// Pipeline: reset -> hist -> scan -> scatter(sort by type) -> tiled GEMM-MLP
//           -> masked per-row reduce.
// ---------------------------------------------------------------------------

#define FFMA2(acc, a, b) \
    asm("fma.rn.f32x2 %0, %1, %2, %0;" : "+l"(acc) : "l"(a), "l"(b))
#define PACK_RR(d, x) \
    asm("mov.b64 %0, {%1, %1};" : "=l"(d) : "r"(x))

__device__ __forceinline__ float f2lo(unsigned long long v) {
    return __uint_as_float((unsigned)v);
}
__device__ __forceinline__ float f2hi(unsigned long long v) {
    return __uint_as_float((unsigned)(v >> 32));
}

constexpr int Bq = 4096, Aq = 64, Fq = 124, Tq = 8, H1q = 64, H2q = 16;
constexpr int NATOM = Bq * Aq;            // 262144
constexpr int TILE  = 128;
constexpr int NTILE = NATOM / TILE;       // 2048
constexpr int FS    = 140;                // featsT row stride (floats): bank-step 3

// scratch (static device memory, allowed)
__device__ int   g_cnt[Tq];
__device__ int   g_off[Tq + 1];
__device__ int   g_fill[Tq];
__device__ int   g_perm[NATOM];
__device__ float g_y[NATOM];
__device__ float g_c[Tq];
__device__ float g_C;

// smem layout (floats) for main kernel
constexpr int SM_FEATS = 0;                       // [124][140]
constexpr int SM_U     = SM_FEATS + Fq * FS;      // 8192: W1s[124][64] / h1T[64][128]
constexpr int SM_W2    = SM_U + 8192;             // [64][16]
constexpr int SM_PART  = SM_W2 + 1024;            // [8][128]
constexpr int SM_B1    = SM_PART + 1024;          // [64]
constexpr int SM_B2    = SM_B1 + 64;              // [16]
constexpr int SM_W3    = SM_B2 + 16;              // [16]
constexpr int SM_PERM  = SM_W3 + 16;              // [128] ints
constexpr int SM_FLOATS = SM_PERM + 128;
constexpr int SMEM_BYTES = SM_FLOATS * 4;         // 111296 B -> 2 CTAs/SM

// ---------------------------------------------------------------------------
__global__ void mol_reset() {
    if (threadIdx.x < Tq) { g_cnt[threadIdx.x] = 0; g_fill[threadIdx.x] = 0; }
}

__global__ void mol_hist(const float* __restrict__ x) {
    __shared__ int h[Tq];
    int tid = threadIdx.x;
    if (tid < Tq) h[tid] = 0;
    __syncthreads();
    int id = blockIdx.x * 512 + tid;
    int t = (int)x[(size_t)id * 125];
    atomicAdd(&h[t], 1);
    __syncthreads();
    if (tid < Tq) atomicAdd(&g_cnt[tid], h[tid]);
}

__global__ void mol_scan() {
    if (threadIdx.x == 0) {
        int s = 0;
        for (int t = 0; t < Tq; t++) { g_off[t] = s; s += g_cnt[t]; }
        g_off[Tq] = s;
    }
}

__global__ void mol_scatter(const float* __restrict__ x) {
    __shared__ int lcnt[Tq], lbase[Tq];
    int tid = threadIdx.x;
    if (tid < Tq) lcnt[tid] = 0;
    __syncthreads();
    int id = blockIdx.x * 512 + tid;
    int t = (int)x[(size_t)id * 125];
    int r = atomicAdd(&lcnt[t], 1);
    __syncthreads();
    if (tid < Tq) lbase[tid] = atomicAdd(&g_fill[tid], lcnt[tid]);
    __syncthreads();
    g_perm[g_off[t] + lbase[t] + r] = id;
}

// ---------------------------------------------------------------------------
__global__ void mol_precompute(const float* __restrict__ b1,
                               const float* __restrict__ W2,
                               const float* __restrict__ b2,
                               const float* __restrict__ W3,
                               const float* __restrict__ b3) {
    __shared__ float cs[Tq];
    int wid = threadIdx.x >> 5, lane = threadIdx.x & 31;
    if (wid < Tq && lane < H2q) {
        int t = wid, g = lane;
        float acc = b2[t * H2q + g];
        #pragma unroll 8
        for (int h = 0; h < H1q; h++) {
            float r = fmaxf(b1[t * H1q + h], 0.f);
            acc = fmaf(r, W2[(t * H1q + h) * H2q + g], acc);
        }
        float p = fmaxf(acc, 0.f) * W3[t * H2q + g];
        p += __shfl_xor_sync(0x0000ffffu, p, 8);
        p += __shfl_xor_sync(0x0000ffffu, p, 4);
        p += __shfl_xor_sync(0x0000ffffu, p, 2);
        p += __shfl_xor_sync(0x0000ffffu, p, 1);
        if (g == 0) cs[t] = p + b3[t];
    }
    __syncthreads();
    if (threadIdx.x == 0) {
        float s = 0.f;
        for (int t = 0; t < Tq; t++) { g_c[t] = cs[t]; s += cs[t]; }
        g_C = s;
    }
}

// ---------------------------------------------------------------------------
// Main: one CTA = 128 sorted atoms.  Register-tiled MLP.
// ---------------------------------------------------------------------------
__global__ __launch_bounds__(256, 2)
void mol_gemm(const float* __restrict__ x,
              const float* __restrict__ W1, const float* __restrict__ b1,
              const float* __restrict__ W2, const float* __restrict__ b2,
              const float* __restrict__ W3, const float* __restrict__ b3) {
    extern __shared__ __align__(16) float sm[];
    float* featsT = sm + SM_FEATS;   // [k][atom], stride FS
    float* W1s    = sm + SM_U;       // [k][64] during layer1
    float* h1T    = sm + SM_U;       // [j][128] after layer1
    float* W2s    = sm + SM_W2;      // [h][16]
    float* partS  = sm + SM_PART;    // [8][128]
    float* b1s    = sm + SM_B1;
    float* b2s    = sm + SM_B2;
    float* w3s    = sm + SM_W3;
    int*   permS  = (int*)(sm + SM_PERM);

    const int tid  = threadIdx.x;
    const int lane = tid & 31;
    const int wid  = tid >> 5;
    const int tx   = lane;           // atom group: atoms tx*4..tx*4+3
    const int ty   = wid;            // out group: layer1 outs ty*8..+7

    const int s = blockIdx.x * TILE;

    if (tid < TILE) permS[tid] = g_perm[s + tid];
    __syncthreads();

    // gather features (coalesced global read, conflict-free column STS)
    for (int i = wid; i < TILE; i += 8) {
        const float* xr = x + (size_t)permS[i] * 125 + 1;
        #pragma unroll
        for (int c = 0; c < 4; c++) {
            int k = lane + 32 * c;
            if (k < Fq) featsT[k * FS + i] = xr[k];
        }
    }

    for (int t = 0; t < Tq; t++) {
        const int r0 = max(g_off[t], s);
        const int r1 = min(g_off[t + 1], s + TILE);
        if (r0 >= r1) continue;       // uniform
        __syncthreads();              // prior pass done / gather visible

        // stage weights for type t
        const float* w1g = W1 + t * (Fq * H1q);
        for (int e = tid; e < Fq * H1q; e += 256) W1s[e] = w1g[e];
        const float* w2g = W2 + t * (H1q * H2q);
        for (int e = tid; e < H1q * H2q; e += 256) W2s[e] = w2g[e];
        if (tid < H1q) b1s[tid] = b1[t * H1q + tid];
        if (tid < H2q) { b2s[tid] = b2[t * H2q + tid]; w3s[tid] = W3[t * H2q + tid]; }
        const float b3v = b3[t];
        const float ct  = g_c[t];
        __syncthreads();

        // ---- layer 1: 128 atoms x 64 outs, K=124
        // thread: atoms tx*4..+3, out-pairs (ty*8+2op, +1), acc packed over outs
        unsigned long long acc[4][4];
        #pragma unroll
        for (int i = 0; i < 4; i++)
            #pragma unroll
            for (int op = 0; op < 4; op++) acc[i][op] = 0ull;

        const float* fp = featsT + tx * 4;
        const float* wp = W1s + ty * 8;
        #pragma unroll 4
        for (int k = 0; k < Fq; k++) {
            float4 a = *(const float4*)(fp + k * FS);
            ulonglong2 bA = *(const ulonglong2*)(wp + k * 64);
            ulonglong2 bB = *(const ulonglong2*)(wp + k * 64 + 4);
            unsigned long long a0, a1, a2, a3;
            PACK_RR(a0, __float_as_uint(a.x));
            PACK_RR(a1, __float_as_uint(a.y));
            PACK_RR(a2, __float_as_uint(a.z));
            PACK_RR(a3, __float_as_uint(a.w));
            FFMA2(acc[0][0], a0, bA.x); FFMA2(acc[0][1], a0, bA.y);
            FFMA2(acc[0][2], a0, bB.x); FFMA2(acc[0][3], a0, bB.y);
            FFMA2(acc[1][0], a1, bA.x); FFMA2(acc[1][1], a1, bA.y);
            FFMA2(acc[1][2], a1, bB.x); FFMA2(acc[1][3], a1, bB.y);
            FFMA2(acc[2][0], a2, bA.x); FFMA2(acc[2][1], a2, bA.y);
            FFMA2(acc[2][2], a2, bB.x); FFMA2(acc[2][3], a2, bB.y);
            FFMA2(acc[3][0], a3, bA.x); FFMA2(acc[3][1], a3, bA.y);
            FFMA2(acc[3][2], a3, bB.x); FFMA2(acc[3][3], a3, bB.y);
        }
        __syncthreads();   // all reads of W1s done before overwrite with h1T

        #pragma unroll
        for (int op = 0; op < 4; op++) {
            int j = ty * 8 + op * 2;
            float bl = b1s[j], bh = b1s[j + 1];
            float4 lo, hi;
            lo.x = fmaxf(f2lo(acc[0][op]) + bl, 0.f);
            lo.y = fmaxf(f2lo(acc[1][op]) + bl, 0.f);
            lo.z = fmaxf(f2lo(acc[2][op]) + bl, 0.f);
            lo.w = fmaxf(f2lo(acc[3][op]) + bl, 0.f);
            hi.x = fmaxf(f2hi(acc[0][op]) + bh, 0.f);
            hi.y = fmaxf(f2hi(acc[1][op]) + bh, 0.f);
            hi.z = fmaxf(f2hi(acc[2][op]) + bh, 0.f);
            hi.w = fmaxf(f2hi(acc[3][op]) + bh, 0.f);
            *(float4*)(h1T + j * 128 + tx * 4)       = lo;
            *(float4*)(h1T + (j + 1) * 128 + tx * 4) = hi;
        }
        __syncthreads();

        // ---- layer 2+3: 128 atoms x 16 outs, K=64; thread: 4 atoms x out-pair ty
        unsigned long long acc2[4] = {0, 0, 0, 0};
        const float* hp = h1T + tx * 4;
        const unsigned long long* w2p =
            (const unsigned long long*)(W2s + ty * 2);
        #pragma unroll 4
        for (int h = 0; h < H1q; h++) {
            float4 a = *(const float4*)(hp + h * 128);
            unsigned long long w = w2p[h * 8];   // 16 floats = 8 ull per row
            unsigned long long a0, a1, a2, a3;
            PACK_RR(a0, __float_as_uint(a.x));
            PACK_RR(a1, __float_as_uint(a.y));
            PACK_RR(a2, __float_as_uint(a.z));
            PACK_RR(a3, __float_as_uint(a.w));
            FFMA2(acc2[0], a0, w); FFMA2(acc2[1], a1, w);
            FFMA2(acc2[2], a2, w); FFMA2(acc2[3], a3, w);
        }
        {
            float b2a = b2s[ty * 2], b2b = b2s[ty * 2 + 1];
            float w3a = w3s[ty * 2], w3b = w3s[ty * 2 + 1];
            float4 pv;
            pv.x = fmaxf(f2lo(acc2[0]) + b2a, 0.f) * w3a + fmaxf(f2hi(acc2[0]) + b2b, 0.f) * w3b;
            pv.y = fmaxf(f2lo(acc2[1]) + b2a, 0.f) * w3a + fmaxf(f2hi(acc2[1]) + b2b, 0.f) * w3b;
            pv.z = fmaxf(f2lo(acc2[2]) + b2a, 0.f) * w3a + fmaxf(f2hi(acc2[2]) + b2b, 0.f) * w3b;
            pv.w = fmaxf(f2lo(acc2[3]) + b2a, 0.f) * w3a + fmaxf(f2hi(acc2[3]) + b2b, 0.f) * w3b;
            *(float4*)(partS + ty * 128 + tx * 4) = pv;
        }
        __syncthreads();

        if (tid < TILE) {
            int row = s + tid;
            if (row >= r0 && row < r1) {
                float p = 0.f;
                #pragma unroll
                for (int q = 0; q < 8; q++) p += partS[q * 128 + tid];
                g_y[permS[tid]] = p + b3v - ct;
            }
        }
    }
}

// ---------------------------------------------------------------------------
__global__ void mol_reduce(const float* __restrict__ mask,
                           float* __restrict__ out) {
    int wid = threadIdx.x >> 5, lane = threadIdx.x & 31;
    int row = blockIdx.x * 8 + wid;
    const float Cv = g_C;
    const float* mr = mask + (size_t)row * Aq;
    const float* yr = g_y + (size_t)row * Aq;
    float v = mr[lane] * (yr[lane] + Cv) + mr[lane + 32] * (yr[lane + 32] + Cv);
    #pragma unroll
    for (int o = 16; o; o >>= 1) v += __shfl_xor_sync(0xffffffffu, v, o);
    if (lane == 0) out[row] = v;
}

// ---------------------------------------------------------------------------
extern "C" void kernel_launch(void* const* d_in, const int* in_sizes, int n_in,
                              void* d_out, int out_size) {
    const float* x  = (const float*)d_in[0];
    const float* mk = (const float*)d_in[1];
    const float* W1 = (const float*)d_in[2];
    const float* b1 = (const float*)d_in[3];
    const float* W2 = (const float*)d_in[4];
    const float* b2 = (const float*)d_in[5];
    const float* W3 = (const float*)d_in[6];
    const float* b3 = (const float*)d_in[7];
    float* out = (float*)d_out;

    cudaFuncSetAttribute(mol_gemm, cudaFuncAttributeMaxDynamicSharedMemorySize,
                         SMEM_BYTES);

    mol_reset<<<1, 32>>>();
    mol_precompute<<<1, 256>>>(b1, W2, b2, W3, b3);
    mol_hist<<<NATOM / 512, 512>>>(x);
    mol_scan<<<1, 32>>>();
    mol_scatter<<<NATOM / 512, 512>>>(x);
    mol_gemm<<<NTILE, 256, SMEM_BYTES>>>(x, W1, b1, W2, b2, W3, b3);
    mol_reduce<<<Bq / 8, 256>>>(mk, out);
}